// round 2
// baseline (speedup 1.0000x reference)
#include <cuda_runtime.h>
#include <float.h>
#include <math.h>

#define N   4096
#define D   256
#define B   4
#define K   20
#define TPB 256
#define VPT (N / TPB)   // 16 values per thread

// Scratch between the two stages (no cudaMalloc allowed).
__device__ float g_w[N * K];
__device__ int   g_idx[N * K];

// ---------------------------------------------------------------------------
// Stage 1: per-row softmax stats + iterative top-20 of the logits.
// One 256-thread block per row; each thread holds 16 logits in registers.
// ---------------------------------------------------------------------------
__global__ __launch_bounds__(TPB) void topk_softmax_kernel(const float* __restrict__ M) {
    const int row  = blockIdx.x;
    const int tid  = threadIdx.x;
    const int lane = tid & 31;
    const int warp = tid >> 5;

    const float* r = M + (size_t)row * N;
    float v[VPT];
#pragma unroll
    for (int j = 0; j < VPT; j++) v[j] = r[tid + j * TPB];   // coalesced

    __shared__ float sred[8];
    __shared__ int   sredc[8];
    __shared__ float s_m, s_s;
    __shared__ int   s_bestc;

    // ---- row max ----
    float m = -FLT_MAX;
#pragma unroll
    for (int j = 0; j < VPT; j++) m = fmaxf(m, v[j]);
#pragma unroll
    for (int off = 16; off; off >>= 1) m = fmaxf(m, __shfl_xor_sync(0xffffffffu, m, off));
    if (lane == 0) sred[warp] = m;
    __syncthreads();
    if (tid == 0) {
        float mm = sred[0];
#pragma unroll
        for (int w = 1; w < 8; w++) mm = fmaxf(mm, sred[w]);
        s_m = mm;
    }
    __syncthreads();
    m = s_m;

    // ---- sum of exp ----
    float s = 0.f;
#pragma unroll
    for (int j = 0; j < VPT; j++) s += __expf(v[j] - m);
#pragma unroll
    for (int off = 16; off; off >>= 1) s += __shfl_xor_sync(0xffffffffu, s, off);
    if (lane == 0) sred[warp] = s;
    __syncthreads();
    if (tid == 0) {
        float ss = 0.f;
#pragma unroll
        for (int w = 0; w < 8; w++) ss += sred[w];
        s_s = ss;
    }
    __syncthreads();
    const float inv_s = 1.0f / s_s;

    // ---- iterative top-K argmax (value, column) ----
    for (int k = 0; k < K; k++) {
        float bv = v[0];
        int   bj = 0;
#pragma unroll
        for (int j = 1; j < VPT; j++)
            if (v[j] > bv) { bv = v[j]; bj = j; }
        int bc = tid + bj * TPB;

#pragma unroll
        for (int off = 16; off; off >>= 1) {
            float ov = __shfl_down_sync(0xffffffffu, bv, off);
            int   oc = __shfl_down_sync(0xffffffffu, bc, off);
            if (ov > bv || (ov == bv && oc < bc)) { bv = ov; bc = oc; }
        }
        if (lane == 0) { sred[warp] = bv; sredc[warp] = bc; }
        __syncthreads();
        if (tid == 0) {
            float fv = sred[0];
            int   fc = sredc[0];
#pragma unroll
            for (int w = 1; w < 8; w++)
                if (sred[w] > fv || (sred[w] == fv && sredc[w] < fc)) { fv = sred[w]; fc = sredc[w]; }
            s_bestc = fc;
            g_idx[row * K + k] = fc;
            g_w[row * K + k]   = __expf(fv - m) * inv_s;
        }
        __syncthreads();
        const int c = s_bestc;
        if ((c & (TPB - 1)) == tid) v[c >> 8] = -FLT_MAX;   // remove winner
    }
}

// ---------------------------------------------------------------------------
// Stage 2: out[b,i,:] = src1[b,i,:] + sum_k w[i,k] * src2[b, idx[i,k], :]
// One block per row i; 256 threads = (b in 0..3) x (64 float4 lanes of D=256).
// K loop fully unrolled -> ~20 outstanding LDG.128 per thread (L2-resident).
// ---------------------------------------------------------------------------
__global__ __launch_bounds__(256) void gather_wsum_kernel(const float* __restrict__ src1,
                                                          const float* __restrict__ src2,
                                                          float* __restrict__ out) {
    const int i   = blockIdx.x;
    const int tid = threadIdx.x;
    const int b   = tid >> 6;    // 0..3
    const int d4  = tid & 63;    // float4 lane

    __shared__ float sw[K];
    __shared__ int   sj[K];
    if (tid < K) { sw[tid] = g_w[i * K + tid]; sj[tid] = g_idx[i * K + tid]; }
    __syncthreads();

    const size_t base = ((size_t)b * N + i) * D;
    float4 acc = ((const float4*)(src1 + base))[d4];
    const float4* s2 = (const float4*)(src2 + (size_t)b * N * D);

#pragma unroll
    for (int k = 0; k < K; k++) {
        const float  w = sw[k];
        const float4 x = s2[(size_t)sj[k] * (D / 4) + d4];
        acc.x = fmaf(w, x.x, acc.x);
        acc.y = fmaf(w, x.y, acc.y);
        acc.z = fmaf(w, x.z, acc.z);
        acc.w = fmaf(w, x.w, acc.w);
    }
    ((float4*)(out + base))[d4] = acc;
}

// ---------------------------------------------------------------------------
extern "C" void kernel_launch(void* const* d_in, const int* in_sizes, int n_in,
                              void* d_out, int out_size) {
    const float* src1 = (const float*)d_in[0];
    const float* src2 = (const float*)d_in[1];
    const float* M    = (const float*)d_in[2];
    float*       out  = (float*)d_out;

    topk_softmax_kernel<<<N, TPB>>>(M);
    gather_wsum_kernel<<<N, 256>>>(src1, src2, out);
}